// round 1
// baseline (speedup 1.0000x reference)
#include <cuda_runtime.h>
#include <math.h>

// Live dataflow of the reference:
//   gu      = 0.2 * x0 * gu0[:,0]                      (fixed, D=100)
//   term3_t = dot(gu, noise[t,:,0]) * sqrt(tlist[t])    (t = 0..39, independent)
//   u_{t+1} = u_t - f(u_t)*tlist[t] + term3_t           (serial scalar chain)
// Output: u_40 (1 float). The per-step MLPs (W1..b3) never reach the output.

#define D 100
#define NSTEPS 40

__device__ __forceinline__ float drift_f(float u) {
    if (u < 50.0f) {
        return -0.02f * u / 3.0f - 0.02f * u;
    } else if (u >= 70.0f) {
        return -0.002f * u / 3.0f - 0.02f * u;
    } else {
        return -(70.0f - 50.0f) / (0.02f - 0.2f) * (u - 50.0f) / 3.0f * u
               - 0.2f / 3.0f * u - 0.02f * u;
    }
}

__global__ void __launch_bounds__(128, 1)
net2_kernel(const float* __restrict__ x0,
            const float* __restrict__ tlist,
            const float* __restrict__ noise,   // (NSTEPS, D, 1) row-major
            const float* __restrict__ u0,
            const float* __restrict__ gu0,     // (D, 1)
            float* __restrict__ out) {
    __shared__ float s_gu[D];
    __shared__ float s_term3[NSTEPS];
    __shared__ float s_dt[NSTEPS];

    const int tid  = threadIdx.x;
    const int lane = tid & 31;
    const int warp = tid >> 5;

    if (tid < D) s_gu[tid] = 0.2f * x0[tid] * gu0[tid];
    if (tid < NSTEPS) s_dt[tid] = tlist[tid];
    __syncthreads();

    // 4 warps x 10 steps each: dot(gu, noise[t]) via shuffle reduce
    for (int t = warp; t < NSTEPS; t += 4) {
        float acc = 0.0f;
        const float* nz = noise + (size_t)t * D;
        #pragma unroll
        for (int i = lane; i < D; i += 32)
            acc += s_gu[i] * nz[i];
        #pragma unroll
        for (int off = 16; off > 0; off >>= 1)
            acc += __shfl_xor_sync(0xffffffffu, acc, off);
        if (lane == 0)
            s_term3[t] = acc * sqrtf(s_dt[t]);
    }
    __syncthreads();

    if (tid == 0) {
        float u = u0[0];
        #pragma unroll
        for (int t = 0; t < NSTEPS; ++t) {
            float dt = s_dt[t];
            u = u - drift_f(u) * dt + s_term3[t];
        }
        out[0] = u;
    }
}

extern "C" void kernel_launch(void* const* d_in, const int* in_sizes, int n_in,
                              void* d_out, int out_size) {
    // metadata order: x0, tlist, noise, u0, gu0, W1, b1, W2, b2, W3, b3
    const float* x0    = (const float*)d_in[0];
    const float* tlist = (const float*)d_in[1];
    const float* noise = (const float*)d_in[2];
    const float* u0    = (const float*)d_in[3];
    const float* gu0   = (const float*)d_in[4];
    float* out = (float*)d_out;
    net2_kernel<<<1, 128>>>(x0, tlist, noise, u0, gu0, out);
}

// round 3
// speedup vs baseline: 1.9231x; 1.9231x over previous
#include <cuda_runtime.h>
#include <math.h>

// Live dataflow of the reference:
//   gu_i    = 0.2 * x0_i * gu0_i                 (fixed, D=100)
//   term3_t = dot(gu, noise[t]) * sqrt(dt_t)     (40 independent dots)
//   u_{t+1} = u_t - f(u_t)*dt_t + term3_t        (serial scalar chain)
// Output: u_40 (1 float). W1..b3 (the per-step MLPs) never reach the output.
//
// R2 (resubmit after infra failure):
//  - 32 warps; warp w handles step w, warps 0..7 also handle step w+32.
//  - All noise loads issued before any reduction -> single latency exposure.
//  - No barrier before the dots (gu computed per-lane from broadcast loads).
//  - Branchless folded recurrence (FSEL instead of branches).

#define D 100
#define NSTEPS 40

__global__ void __launch_bounds__(1024, 1)
net2_kernel(const float* __restrict__ x0,
            const float* __restrict__ tlist,
            const float* __restrict__ noise,   // (NSTEPS, D)
            const float* __restrict__ u0,
            const float* __restrict__ gu0,     // (D, 1)
            float* __restrict__ out) {
    __shared__ float s_term3[NSTEPS];
    __shared__ float s_dt[NSTEPS];
    __shared__ float s_Al[NSTEPS];   // 1 + (0.02/3 + 0.02)*dt
    __shared__ float s_Ah[NSTEPS];   // 1 + (0.002/3 + 0.02)*dt

    const int tid  = threadIdx.x;
    const int lane = tid & 31;
    const int warp = tid >> 5;

    if (tid < NSTEPS) {
        float dt = tlist[tid];
        s_dt[tid] = dt;
        s_Al[tid] = fmaf(0.026666667f, dt, 1.0f);
        s_Ah[tid] = fmaf(0.020666667f, dt, 1.0f);
    }

    // Per-warp dt loads for the sqrt scale (L1 broadcast, issued early).
    const int t0 = warp;
    const int t1 = warp + 32;
    const bool two = (warp < NSTEPS - 32);
    const float dt0 = tlist[t0];
    const float dt1 = two ? tlist[t1] : 0.0f;

    // gu for this lane's 4 strided slots (same lines for every warp -> L1).
    float g0 = 0.2f * x0[lane]      * gu0[lane];
    float g1 = 0.2f * x0[lane + 32] * gu0[lane + 32];
    float g2 = 0.2f * x0[lane + 64] * gu0[lane + 64];
    float g3 = (lane < D - 96) ? 0.2f * x0[lane + 96] * gu0[lane + 96] : 0.0f;

    // Issue ALL noise loads before any reduction so every load is in flight.
    const float* nz0 = noise + t0 * D;
    float a0 = nz0[lane];
    float a1 = nz0[lane + 32];
    float a2 = nz0[lane + 64];
    float a3 = (lane < D - 96) ? nz0[lane + 96] : 0.0f;

    float b0 = 0.0f, b1 = 0.0f, b2 = 0.0f, b3 = 0.0f;
    if (two) {
        const float* nz1 = noise + t1 * D;
        b0 = nz1[lane];
        b1 = nz1[lane + 32];
        b2 = nz1[lane + 64];
        b3 = (lane < D - 96) ? nz1[lane + 96] : 0.0f;
    }

    float acc = g0 * a0 + g1 * a1 + g2 * a2 + g3 * a3;
    #pragma unroll
    for (int off = 16; off > 0; off >>= 1)
        acc += __shfl_xor_sync(0xffffffffu, acc, off);
    if (lane == 0)
        s_term3[t0] = acc * sqrtf(dt0);

    if (two) {
        float acc1 = g0 * b0 + g1 * b1 + g2 * b2 + g3 * b3;
        #pragma unroll
        for (int off = 16; off > 0; off >>= 1)
            acc1 += __shfl_xor_sync(0xffffffffu, acc1, off);
        if (lane == 0)
            s_term3[t1] = acc1 * sqrtf(dt1);
    }

    __syncthreads();

    if (tid == 0) {
        float u = u0[0];
        #pragma unroll
        for (int t = 0; t < NSTEPS; ++t) {
            const float T  = s_term3[t];
            const float dt = s_dt[t];
            // low (u < 50):   u' = u*(1 + 0.0266667*dt) + T
            const float ul = fmaf(u, s_Al[t], T);
            // high (u >= 70): u' = u*(1 + 0.0206667*dt) + T
            const float uh = fmaf(u, s_Ah[t], T);
            // mid: f(u) = u*(37.037037*(u-50) - 0.0866667)   ((u-50) exact near 50)
            const float um50 = u - 50.0f;
            const float p  = fmaf(37.037037f, um50, -0.086666667f);
            const float g  = u * p;
            const float s  = u + T;                 // off the critical path
            const float um = fmaf(-dt, g, s);
            u = (u < 50.0f) ? ul : ((u >= 70.0f) ? uh : um);
        }
        out[0] = u;
    }
}

extern "C" void kernel_launch(void* const* d_in, const int* in_sizes, int n_in,
                              void* d_out, int out_size) {
    // metadata order: x0, tlist, noise, u0, gu0, W1, b1, W2, b2, W3, b3
    const float* x0    = (const float*)d_in[0];
    const float* tlist = (const float*)d_in[1];
    const float* noise = (const float*)d_in[2];
    const float* u0    = (const float*)d_in[3];
    const float* gu0   = (const float*)d_in[4];
    float* out = (float*)d_out;
    net2_kernel<<<1, 1024>>>(x0, tlist, noise, u0, gu0, out);
}

// round 5
// speedup vs baseline: 1.9324x; 1.0048x over previous
#include <cuda_runtime.h>
#include <math.h>

// Live dataflow of the reference:
//   gu_i    = 0.2 * x0_i * gu0_i                 (fixed, D=100)
//   term3_t = dot(gu, noise[t]) * sqrt(dt_t)     (40 independent dots)
//   u_{t+1} = u_t - f(u_t)*dt_t + term3_t        (serial scalar chain)
// Output: u_40 (1 float). W1..b3 (the per-step MLPs) never reach the output.
//
// R4 (resubmit after broker timeout): 640 threads (20 warps x 2 steps),
// float4 loads (25 LDG.128 per step), all loads in flight before any
// reduction, branchless folded recurrence.

#define D 100
#define NSTEPS 40
#define NF4 25          // float4s per row (100 floats)

__device__ __forceinline__ float dot4(float4 a, float4 b) {
    return fmaf(a.x, b.x, fmaf(a.y, b.y, fmaf(a.z, b.z, a.w * b.w)));
}

__global__ void __launch_bounds__(640, 1)
net2_kernel(const float* __restrict__ x0,
            const float* __restrict__ tlist,
            const float* __restrict__ noise,   // (NSTEPS, D), rows 400B = 16B aligned
            const float* __restrict__ u0,
            const float* __restrict__ gu0,     // (D, 1)
            float* __restrict__ out) {
    __shared__ float s_term3[NSTEPS];
    __shared__ float s_dt[NSTEPS];
    __shared__ float s_Al[NSTEPS];   // 1 + (0.02/3 + 0.02)*dt
    __shared__ float s_Ah[NSTEPS];   // 1 + (0.002/3 + 0.02)*dt

    const int tid  = threadIdx.x;
    const int lane = tid & 31;
    const int warp = tid >> 5;       // 0..19

    if (tid < NSTEPS) {
        float dt = tlist[tid];
        s_dt[tid] = dt;
        s_Al[tid] = fmaf(0.026666667f, dt, 1.0f);
        s_Ah[tid] = fmaf(0.020666667f, dt, 1.0f);
    }

    const int t0 = warp * 2;
    const int t1 = t0 + 1;
    const float dt0 = tlist[t0];     // L1-broadcast, off critical path
    const float dt1 = tlist[t1];

    const float4* x0f  = (const float4*)x0;
    const float4* guf  = (const float4*)gu0;
    const float4* nzf  = (const float4*)noise;

    // Issue ALL loads before any arithmetic/reduction.
    float4 g4 = make_float4(0.f, 0.f, 0.f, 0.f);
    float4 n0 = make_float4(0.f, 0.f, 0.f, 0.f);
    float4 n1 = make_float4(0.f, 0.f, 0.f, 0.f);
    if (lane < NF4) {
        float4 xv = x0f[lane];
        float4 gv = guf[lane];
        n0 = nzf[t0 * NF4 + lane];
        n1 = nzf[t1 * NF4 + lane];
        g4 = make_float4(0.2f * xv.x * gv.x, 0.2f * xv.y * gv.y,
                         0.2f * xv.z * gv.z, 0.2f * xv.w * gv.w);
    }

    float acc0 = dot4(g4, n0);
    #pragma unroll
    for (int off = 16; off > 0; off >>= 1)
        acc0 += __shfl_xor_sync(0xffffffffu, acc0, off);
    if (lane == 0)
        s_term3[t0] = acc0 * sqrtf(dt0);

    float acc1 = dot4(g4, n1);
    #pragma unroll
    for (int off = 16; off > 0; off >>= 1)
        acc1 += __shfl_xor_sync(0xffffffffu, acc1, off);
    if (lane == 0)
        s_term3[t1] = acc1 * sqrtf(dt1);

    __syncthreads();

    if (tid == 0) {
        float u = u0[0];
        #pragma unroll
        for (int t = 0; t < NSTEPS; ++t) {
            const float T  = s_term3[t];
            const float dt = s_dt[t];
            // low (u < 50):   u' = u*(1 + 0.0266667*dt) + T
            const float ul = fmaf(u, s_Al[t], T);
            // high (u >= 70): u' = u*(1 + 0.0206667*dt) + T
            const float uh = fmaf(u, s_Ah[t], T);
            // mid: f(u) = u*(37.037037*(u-50) - 0.0866667)   ((u-50) exact near 50)
            const float um50 = u - 50.0f;
            const float p  = fmaf(37.037037f, um50, -0.086666667f);
            const float g  = u * p;
            const float s  = u + T;                 // off the critical path
            const float um = fmaf(-dt, g, s);
            u = (u < 50.0f) ? ul : ((u >= 70.0f) ? uh : um);
        }
        out[0] = u;
    }
}

extern "C" void kernel_launch(void* const* d_in, const int* in_sizes, int n_in,
                              void* d_out, int out_size) {
    // metadata order: x0, tlist, noise, u0, gu0, W1, b1, W2, b2, W3, b3
    const float* x0    = (const float*)d_in[0];
    const float* tlist = (const float*)d_in[1];
    const float* noise = (const float*)d_in[2];
    const float* u0    = (const float*)d_in[3];
    const float* gu0   = (const float*)d_in[4];
    float* out = (float*)d_out;
    net2_kernel<<<1, 640>>>(x0, tlist, noise, u0, gu0, out);
}